// round 13
// baseline (speedup 1.0000x reference)
#include <cuda_runtime.h>
#include <cuda_bf16.h>
#include <math.h>
#include <stdint.h>

#define BB 64
#define TT 4096
#define DD 90
#define KK 32
#define CC 256           // chunks per batch
#define CHUNK 16         // TT / CC
#define WARM 8           // burn-in steps (contraction 0.46^8 ~ 2e-3 per chunk)
#define NSTEP (WARM + CHUNK)     // 24
#define PADF 8           // MUST == WARM (scan reads rows without +PADF -> -WARM shift)
#define PADB 8
#define ERows (PADF + TT + PADB) // 4112 rows per batch
#define NEB (BB * TT / 128)      // 2048 emission blocks
#define NSB (BB * CC / 64)       // 256 scan blocks (4 warps x 2 chunk-rows each)
#define LOG2PI_F 1.8378770664093453f
#define FULLMASK 0xffffffffu

// ---- scratch (__device__ globals; no allocations allowed) ----
__device__ __align__(16) __nv_bfloat16 g_ee16[BB * ERows * KK]; // exp(em-emax), bf16, col-permuted
__device__ __align__(16) uint2 g_Wb[12 * 4 * 32];        // bf16 B-fragment table
__device__ __align__(16) float g_bias[KK];
__device__ float g_pi[KK];
__device__ float g_expA[KK * KK];
__device__ __align__(16) float g_partial2[BB * CC];      // 16384 per-chunk log factors
__device__ __align__(16) float g_emaxpart[NEB];          // per-emis-block emax sums
__device__ unsigned g_ctr;                                // scan completion counter (wraps)

__device__ __forceinline__ float warpMax(float v) {
#pragma unroll
    for (int o = 16; o > 0; o >>= 1) v = fmaxf(v, __shfl_xor_sync(FULLMASK, v, o));
    return v;
}
__device__ __forceinline__ float warpSum(float v) {
#pragma unroll
    for (int o = 16; o > 0; o >>= 1) v += __shfl_xor_sync(FULLMASK, v, o);
    return v;
}
__device__ __forceinline__ uint32_t packbf2(float lo, float hi) {
    __nv_bfloat162 h = __floats2bfloat162_rn(lo, hi);
    return *reinterpret_cast<uint32_t*>(&h);
}
__device__ __forceinline__ __nv_bfloat162 bfu(uint32_t v) {
    return *reinterpret_cast<__nv_bfloat162*>(&v);
}
__device__ __forceinline__ uint32_t ubf(__nv_bfloat162 h) {
    return *reinterpret_cast<uint32_t*>(&h);
}
__device__ __forceinline__ uint32_t sqbf2(uint32_t v) {   // bf16x2 -> bf16x2 of squares
    float2 f = __bfloat1622float2(bfu(v));
    return packbf2(f.x * f.x, f.y * f.y);
}
__device__ __forceinline__ void mma_bf16(float& d0, float& d1, float& d2, float& d3,
                                         uint32_t a0, uint32_t a1, uint32_t a2, uint32_t a3,
                                         uint32_t b0, uint32_t b1) {
    asm volatile("mma.sync.aligned.m16n8k16.row.col.f32.bf16.bf16.f32 "
                 "{%0,%1,%2,%3},{%4,%5,%6,%7},{%8,%9},{%0,%1,%2,%3};"
                 : "+f"(d0), "+f"(d1), "+f"(d2), "+f"(d3)
                 : "r"(a0), "r"(a1), "r"(a2), "r"(a3), "r"(b0), "r"(b1));
}
__device__ __forceinline__ void mma_bf16_z(float* d,
                                           uint32_t a0, uint32_t a1, uint32_t a2, uint32_t a3,
                                           uint32_t b0, uint32_t b1) {
    asm volatile("mma.sync.aligned.m16n8k16.row.col.f32.bf16.bf16.f32 "
                 "{%0,%1,%2,%3},{%4,%5,%6,%7},{%8,%9},{%10,%10,%10,%10};"
                 : "=f"(d[0]), "=f"(d[1]), "=f"(d[2]), "=f"(d[3])
                 : "r"(a0), "r"(a1), "r"(a2), "r"(a3), "r"(b0), "r"(b1), "f"(0.0f));
}

// ---------------------------------------------------------------------------
// Kernel 1: prep — grid 8 x 256.
// ---------------------------------------------------------------------------
__global__ void __launch_bounds__(256) hmm_prep_kernel(
        const float* __restrict__ sp, const float* __restrict__ trans,
        const float* __restrict__ mu, const float* __restrict__ log_var) {
    cudaTriggerProgrammaticLaunchCompletion();
    int tid = threadIdx.x, wid = tid >> 5, lane = tid & 31;
    int gw = blockIdx.x * 8 + wid;

    if (gw < 32) {
        float v = trans[gw * KK + lane];
        float m = warpMax(v);
        float e = expf(v - m);
        float s = warpSum(e);
        g_expA[gw * KK + lane] = e / s;
        if (gw == 0) {
            float pv = sp[lane];
            float pm = warpMax(pv);
            float pe = expf(pv - pm);
            float ps = warpSum(pe);
            g_pi[lane] = pe / ps;
        }
    } else {
        int k = gw - 32;
        float acc = 0.0f;
        for (int d = lane; d < DD; d += 32) {
            float lv = log_var[k * DD + d];
            float iv = expf(-lv);
            float m = mu[k * DD + d];
            acc = fmaf(m * m, iv, acc + lv);
        }
        acc = warpSum(acc);
        if (lane == 0) g_bias[k] = -0.5f * (acc + (float)DD * LOG2PI_F);
    }

    int p = blockIdx.x * 256 + tid;
    if (p < 12 * 4 * 32) {
        int s = p >> 7;
        int rem = p & 127;
        int ln = rem & 31;
        int gid = ln >> 2, tig = ln & 3;
        int n = (rem >> 5) * 8 + gid;
        float w[4];
#pragma unroll
        for (int h = 0; h < 4; ++h) {
            int row = s * 16 + tig * 2 + (h >> 1) * 8 + (h & 1);
            float v = 0.f;
            if (row < 96) {
                int d = row;
                if (d < DD) v = mu[n * DD + d] * expf(-log_var[n * DD + d]);
            } else {
                int d = row - 96;
                if (d < DD) v = -0.5f * expf(-log_var[n * DD + d]);
            }
            w[h] = v;
        }
        g_Wb[p] = make_uint2(packbf2(w[0], w[1]), packbf2(w[2], w[3]));
    }
}

// ---------------------------------------------------------------------------
// Kernel 2: emissions (bf16 MMA). X staged in smem AS BF16 (23 KB).
// ---------------------------------------------------------------------------
__global__ void __launch_bounds__(256) hmm_emis_kernel(const float* __restrict__ X) {
    cudaTriggerProgrammaticLaunchCompletion();
    __shared__ __align__(16) uint32_t xsb[128 * 45];   // 23.04 KB
    __shared__ __align__(16) uint2 ws[12 * 4 * 32];    // 12 KB
    __shared__ __align__(8) float sbias[KK];
    __shared__ float mred[8];

    int tid = threadIdx.x;
    int wid = tid >> 5, lane = tid & 31;
    int gid = lane >> 2, tig = lane & 3;

    {   // stage X tile (f32 -> bf16x2 on the fly) — independent of prep
        const float4* X4 = (const float4*)(X + (long)blockIdx.x * 128 * DD);
        uint2* xs2 = (uint2*)xsb;
#pragma unroll
        for (int i = 0; i < 11; ++i) {
            float4 v = X4[tid + 256 * i];
            xs2[tid + 256 * i] = make_uint2(packbf2(v.x, v.y), packbf2(v.z, v.w));
        }
        if (tid < 2880 - 2816) {
            float4 v = X4[tid + 2816];
            xs2[tid + 2816] = make_uint2(packbf2(v.x, v.y), packbf2(v.z, v.w));
        }
    }
    cudaGridDependencySynchronize();     // wait for prep's g_Wb / g_bias
    {
        const uint4* src = (const uint4*)g_Wb;
        uint4* dst = (uint4*)ws;
#pragma unroll
        for (int i = 0; i < 3; ++i) dst[tid + 256 * i] = src[tid + 256 * i];
        if (tid < KK) sbias[tid] = g_bias[tid];
    }
    __syncthreads();

    const uint32_t* xr0 = xsb + (wid * 16 + gid) * 45;
    const uint32_t* xr1 = xr0 + 8 * 45;

    float acc[4][4];
#pragma unroll
    for (int nt = 0; nt < 4; ++nt)
#pragma unroll
        for (int i = 0; i < 4; ++i) acc[nt][i] = 0.f;

#pragma unroll
    for (int s = 0; s < 6; ++s) {
        int w0 = s * 8 + tig;
        int w1 = w0 + 4;
        bool v1 = (s * 16 + tig * 2 + 8) < DD;
        uint32_t a0 = xr0[w0];
        uint32_t a1 = xr1[w0];
        uint32_t a2 = v1 ? xr0[w1] : 0u;
        uint32_t a3 = v1 ? xr1[w1] : 0u;
        uint32_t q0 = sqbf2(a0), q1 = sqbf2(a1), q2 = sqbf2(a2), q3 = sqbf2(a3);
#pragma unroll
        for (int nt = 0; nt < 4; ++nt) {
            uint2 bb = ws[(s * 4 + nt) * 32 + lane];
            mma_bf16(acc[nt][0], acc[nt][1], acc[nt][2], acc[nt][3],
                     a0, a1, a2, a3, bb.x, bb.y);
        }
#pragma unroll
        for (int nt = 0; nt < 4; ++nt) {
            uint2 bb = ws[((s + 6) * 4 + nt) * 32 + lane];
            mma_bf16(acc[nt][0], acc[nt][1], acc[nt][2], acc[nt][3],
                     q0, q1, q2, q3, bb.x, bb.y);
        }
    }

    const float2* sb2 = (const float2*)sbias;
    float m0 = -1e30f, m1 = -1e30f;
#pragma unroll
    for (int nt = 0; nt < 4; ++nt) {
        float2 bv = sb2[nt * 4 + tig];
        acc[nt][0] += bv.x; acc[nt][1] += bv.y;
        acc[nt][2] += bv.x; acc[nt][3] += bv.y;
        m0 = fmaxf(m0, fmaxf(acc[nt][0], acc[nt][1]));
        m1 = fmaxf(m1, fmaxf(acc[nt][2], acc[nt][3]));
    }
#pragma unroll
    for (int o = 1; o <= 2; o <<= 1) {
        m0 = fmaxf(m0, __shfl_xor_sync(FULLMASK, m0, o));
        m1 = fmaxf(m1, __shfl_xor_sync(FULLMASK, m1, o));
    }
    long r0 = (long)(blockIdx.x >> 5) * ERows + PADF
            + (blockIdx.x & 31) * 128 + wid * 16 + gid;
    long r1 = r0 + 8;
    uint4 o0, o1;
    o0.x = packbf2(__expf(acc[0][0] - m0), __expf(acc[0][1] - m0));
    o0.y = packbf2(__expf(acc[1][0] - m0), __expf(acc[1][1] - m0));
    o0.z = packbf2(__expf(acc[2][0] - m0), __expf(acc[2][1] - m0));
    o0.w = packbf2(__expf(acc[3][0] - m0), __expf(acc[3][1] - m0));
    o1.x = packbf2(__expf(acc[0][2] - m1), __expf(acc[0][3] - m1));
    o1.y = packbf2(__expf(acc[1][2] - m1), __expf(acc[1][3] - m1));
    o1.z = packbf2(__expf(acc[2][2] - m1), __expf(acc[2][3] - m1));
    o1.w = packbf2(__expf(acc[3][2] - m1), __expf(acc[3][3] - m1));
    ((uint4*)(g_ee16 + r0 * KK))[tig] = o0;
    ((uint4*)(g_ee16 + r1 * KK))[tig] = o1;

    float msum = (tig == 0) ? (m0 + m1) : 0.f;
    msum = warpSum(msum);
    if (lane == 0) mred[wid] = msum;
    __syncthreads();
    if (tid == 0) {
        float s = 0.f;
#pragma unroll
        for (int i = 0; i < 8; ++i) s += mred[i];
        g_emaxpart[blockIdx.x] = s;
    }
}

// ---------------------------------------------------------------------------
// Kernel 3: tensor-core chunked scan, CC=256, NSTEP=24. Last-arriving block
// performs the deterministic fixed-order final reduction (fused kernel 4).
// ---------------------------------------------------------------------------
__global__ void __launch_bounds__(128) hmm_scan_kernel(float* __restrict__ out) {
    cudaTriggerProgrammaticLaunchCompletion();
    cudaGridDependencySynchronize();     // wait for emission (and transitively prep)
    int wid = threadIdx.x >> 5;
    int w = blockIdx.x * 4 + wid;        // 0..1023
    int lane = threadIdx.x & 31;
    int gid = lane >> 2, tig = lane & 3;
    int b = w >> 4;                      // 16 warps per batch
    int g = w & 15;
    int c0 = g * 16 + gid;               // 0..247
    int c1 = c0 + 8;                     // 8..255
    const __nv_bfloat16* eb = g_ee16 + (long)b * (ERows * KK);

    uint32_t Bf[8][2];
#pragma unroll
    for (int ks = 0; ks < 2; ++ks)
#pragma unroll
        for (int nt = 0; nt < 4; ++nt) {
            int n = nt * 8 + gid;
            int r = ks * 16 + 2 * tig;
            Bf[ks * 4 + nt][0] = packbf2(g_expA[r * KK + n], g_expA[(r + 1) * KK + n]);
            Bf[ks * 4 + nt][1] = packbf2(g_expA[(r + 8) * KK + n], g_expA[(r + 9) * KK + n]);
        }

    uint32_t pk[4][2];
    {
        uint4 ei = ((const uint4*)(eb + (long)PADF * KK))[tig];
        uint32_t ec[4] = {ei.x, ei.y, ei.z, ei.w};
#pragma unroll
        for (int nt = 0; nt < 4; ++nt) {
            float i00 = 1.f, i01 = 1.f;
            if (c0 == 0) {
                float2 ef = __bfloat1622float2(bfu(ec[nt]));
                i00 = g_pi[nt * 8 + 2 * tig] * ef.x;
                i01 = g_pi[nt * 8 + 2 * tig + 1] * ef.y;
            }
            pk[nt][0] = packbf2(i00, i01);
            pk[nt][1] = packbf2(1.f, 1.f);
        }
    }

    int ilo0 = (c0 == 0) ? WARM : 0;
    int ihi1 = (c1 == CC - 1) ? (NSTEP - 1) : NSTEP;

    const __nv_bfloat16* pe0 = eb + (long)(c0 * CHUNK + 1) * KK;
    const __nv_bfloat16* pe1 = eb + (long)(c1 * CHUNK + 1) * KK;

    uint4 ring0[4], ring1[4];
#pragma unroll
    for (int s = 0; s < 4; ++s) {
        ring0[s] = ((const uint4*)(pe0 + (long)s * KK))[tig];
        ring1[s] = ((const uint4*)(pe1 + (long)s * KK))[tig];
    }

    float logZ0 = 0.f, logZ1 = 0.f;
    for (int blk = 0; blk < NSTEP / 8; ++blk) {      // 3 blocks
        const __nv_bfloat16* q0 = pe0 + (long)(blk * 8 + 4) * KK;
        const __nv_bfloat16* q1 = pe1 + (long)(blk * 8 + 4) * KK;
        bool doLog = (blk >= WARM / 8);
#pragma unroll
        for (int ii = 0; ii < 8; ++ii) {
            int i = blk * 8 + ii;
            float dA[4][4], dB[4][4];
#pragma unroll
            for (int nt = 0; nt < 4; ++nt)
                mma_bf16_z(dA[nt], pk[0][0], pk[0][1], pk[1][0], pk[1][1],
                           Bf[nt][0], Bf[nt][1]);
#pragma unroll
            for (int nt = 0; nt < 4; ++nt)
                mma_bf16_z(dB[nt], pk[2][0], pk[2][1], pk[3][0], pk[3][1],
                           Bf[4 + nt][0], Bf[4 + nt][1]);

            const int slot = ii & 3;
            uint4 e0 = ring0[slot], e1 = ring1[slot];
            ring0[slot] = ((const uint4*)(q0 + (long)ii * KK))[tig];
            ring1[slot] = ((const uint4*)(q1 + (long)ii * KK))[tig];
            uint32_t ec0[4] = {e0.x, e0.y, e0.z, e0.w};
            uint32_t ec1[4] = {e1.x, e1.y, e1.z, e1.w};

            __nv_bfloat162 n0[4], n1[4];
#pragma unroll
            for (int nt = 0; nt < 4; ++nt) {
                __nv_bfloat162 d0 = __floats2bfloat162_rn(dA[nt][0] + dB[nt][0],
                                                          dA[nt][1] + dB[nt][1]);
                __nv_bfloat162 d1 = __floats2bfloat162_rn(dA[nt][2] + dB[nt][2],
                                                          dA[nt][3] + dB[nt][3]);
                n0[nt] = __hmul2(d0, bfu(ec0[nt]));
                n1[nt] = __hmul2(d1, bfu(ec1[nt]));
            }

            bool val0 = (i >= ilo0);
            bool val1 = (i < ihi1);
            if (ii == 7) {
                float S0 = 0.f, S1 = 0.f;
#pragma unroll
                for (int nt = 0; nt < 4; ++nt) {
                    float2 a = __bfloat1622float2(n0[nt]);
                    float2 c = __bfloat1622float2(n1[nt]);
                    S0 += a.x + a.y;
                    S1 += c.x + c.y;
                }
#pragma unroll
                for (int o = 1; o <= 2; o <<= 1) {
                    S0 += __shfl_xor_sync(FULLMASK, S0, o);
                    S1 += __shfl_xor_sync(FULLMASK, S1, o);
                }
                bool ren0 = val0 && (doLog || c0 != 0);
                bool ren1 = val1;
                float sc0 = ren0 ? __frcp_rn(S0) : 1.f;
                float sc1 = ren1 ? __frcp_rn(S1) : 1.f;
                if (doLog && val0) logZ0 += __logf(S0);
                if (doLog && val1) logZ1 += __logf(S1);
                __nv_bfloat162 sb0 = __float2bfloat162_rn(sc0);
                __nv_bfloat162 sb1 = __float2bfloat162_rn(sc1);
#pragma unroll
                for (int nt = 0; nt < 4; ++nt) {
                    n0[nt] = __hmul2(n0[nt], sb0);
                    n1[nt] = __hmul2(n1[nt], sb1);
                }
            }
#pragma unroll
            for (int nt = 0; nt < 4; ++nt) {
                pk[nt][0] = val0 ? ubf(n0[nt]) : pk[nt][0];
                pk[nt][1] = val1 ? ubf(n1[nt]) : pk[nt][1];
            }
        }
    }

    float S0 = 0.f, S1 = 0.f;
#pragma unroll
    for (int nt = 0; nt < 4; ++nt) {
        float2 a = __bfloat1622float2(bfu(pk[nt][0]));
        float2 c = __bfloat1622float2(bfu(pk[nt][1]));
        S0 += a.x + a.y;
        S1 += c.x + c.y;
    }
#pragma unroll
    for (int o = 1; o <= 2; o <<= 1) {
        S0 += __shfl_xor_sync(FULLMASK, S0, o);
        S1 += __shfl_xor_sync(FULLMASK, S1, o);
    }
    if (tig == 0) {
        g_partial2[b * CC + c0] = logZ0 + __logf(S0);
        g_partial2[b * CC + c1] = logZ1 + __logf(S1);
    }

    // ---- fused deterministic final reduction (last block to arrive) ----
    __threadfence();
    __syncthreads();                         // all 4 warps' stores issued
    __shared__ unsigned sIsLast;
    if (threadIdx.x == 0) {
        unsigned old = atomicInc(&g_ctr, NSB - 1);   // wraps back to 0
        sIsLast = (old == NSB - 1) ? 1u : 0u;
    }
    __syncthreads();
    if (sIsLast) {
        __threadfence();
        __shared__ double red[4];
        int tid = threadIdx.x;
        double v = 0.0;
        const float4* p2 = (const float4*)g_partial2;
        const float4* pe = (const float4*)g_emaxpart;
        for (int i = tid; i < BB * CC / 4; i += 128) {
            float4 a = p2[i];
            v += (double)a.x + (double)a.y + (double)a.z + (double)a.w;
        }
        for (int i = tid; i < NEB / 4; i += 128) {
            float4 a = pe[i];
            v += (double)a.x + (double)a.y + (double)a.z + (double)a.w;
        }
#pragma unroll
        for (int o = 16; o > 0; o >>= 1) v += __shfl_xor_sync(FULLMASK, v, o);
        if ((tid & 31) == 0) red[tid >> 5] = v;
        __syncthreads();
        if (tid < 4) {
            double wv = red[tid];
            wv += __shfl_xor_sync(0xf, wv, 1);
            wv += __shfl_xor_sync(0xf, wv, 2);
            if (tid == 0) out[0] = (float)wv;
        }
    }
}

// ---------------------------------------------------------------------------
extern "C" void kernel_launch(void* const* d_in, const int* in_sizes, int n_in,
                              void* d_out, int out_size) {
    const float* X = (const float*)d_in[0];
    const float* sp = (const float*)d_in[1];
    const float* trans = (const float*)d_in[2];
    const float* mu = (const float*)d_in[3];
    const float* log_var = (const float*)d_in[4];

    hmm_prep_kernel<<<8, 256>>>(sp, trans, mu, log_var);

    cudaLaunchAttribute at[1];
    at[0].id = cudaLaunchAttributeProgrammaticStreamSerialization;
    at[0].val.programmaticStreamSerializationAllowed = 1;

    cudaLaunchConfig_t cfg = {};
    cfg.attrs = at;
    cfg.numAttrs = 1;
    cfg.stream = 0;

    cfg.gridDim = dim3(NEB);
    cfg.blockDim = dim3(256);
    cudaLaunchKernelEx(&cfg, hmm_emis_kernel, X);

    cfg.gridDim = dim3(NSB);             // 256 blocks x 4 warps
    cfg.blockDim = dim3(128);
    float* outp = (float*)d_out;
    cudaLaunchKernelEx(&cfg, hmm_scan_kernel, outp);
}

// round 14
// speedup vs baseline: 1.0368x; 1.0368x over previous
#include <cuda_runtime.h>
#include <cuda_bf16.h>
#include <math.h>
#include <stdint.h>

#define BB 64
#define TT 4096
#define DD 90
#define KK 32
#define CC 256           // chunks per batch
#define CHUNK 16         // TT / CC
#define WARM 8           // burn-in steps (contraction 0.46^8 ~ 2e-3 per chunk)
#define NSTEP (WARM + CHUNK)     // 24
#define PADF 8           // MUST == WARM (scan reads rows without +PADF -> -WARM shift)
#define PADB 8
#define ERows (PADF + TT + PADB) // 4112 rows per batch
#define NEB (BB * TT / 128)      // 2048 emission blocks
#define NSB (BB * CC / 64)       // 256 scan blocks (4 warps, 16 chains each)
#define LOG2PI_F 1.8378770664093453f
#define FULLMASK 0xffffffffu

// ---- scratch (__device__ globals; no allocations allowed) ----
__device__ __align__(16) __nv_bfloat16 g_ee16[BB * ERows * KK]; // exp(em-emax), bf16, col-permuted
__device__ __align__(16) uint2 g_Wb[12 * 4 * 32];        // bf16 B-fragment table
__device__ __align__(16) float g_bias[KK];
__device__ float g_pi[KK];
__device__ float g_expA[KK * KK];
__device__ __align__(16) float g_partial2[BB * CC];      // 16384 per-chunk log factors
__device__ __align__(16) float g_emaxpart[NEB];          // per-emis-block emax sums

__device__ __forceinline__ float warpMax(float v) {
#pragma unroll
    for (int o = 16; o > 0; o >>= 1) v = fmaxf(v, __shfl_xor_sync(FULLMASK, v, o));
    return v;
}
__device__ __forceinline__ float warpSum(float v) {
#pragma unroll
    for (int o = 16; o > 0; o >>= 1) v += __shfl_xor_sync(FULLMASK, v, o);
    return v;
}
__device__ __forceinline__ uint32_t packbf2(float lo, float hi) {
    __nv_bfloat162 h = __floats2bfloat162_rn(lo, hi);
    return *reinterpret_cast<uint32_t*>(&h);
}
__device__ __forceinline__ __nv_bfloat162 bfu(uint32_t v) {
    return *reinterpret_cast<__nv_bfloat162*>(&v);
}
__device__ __forceinline__ uint32_t ubf(__nv_bfloat162 h) {
    return *reinterpret_cast<uint32_t*>(&h);
}
__device__ __forceinline__ uint32_t sqbf2(uint32_t v) {   // bf16x2 -> bf16x2 of squares
    float2 f = __bfloat1622float2(bfu(v));
    return packbf2(f.x * f.x, f.y * f.y);
}
__device__ __forceinline__ void mma_bf16(float& d0, float& d1, float& d2, float& d3,
                                         uint32_t a0, uint32_t a1, uint32_t a2, uint32_t a3,
                                         uint32_t b0, uint32_t b1) {
    asm volatile("mma.sync.aligned.m16n8k16.row.col.f32.bf16.bf16.f32 "
                 "{%0,%1,%2,%3},{%4,%5,%6,%7},{%8,%9},{%0,%1,%2,%3};"
                 : "+f"(d0), "+f"(d1), "+f"(d2), "+f"(d3)
                 : "r"(a0), "r"(a1), "r"(a2), "r"(a3), "r"(b0), "r"(b1));
}
__device__ __forceinline__ void mma_bf16_z(float* d,
                                           uint32_t a0, uint32_t a1, uint32_t a2, uint32_t a3,
                                           uint32_t b0, uint32_t b1) {
    asm volatile("mma.sync.aligned.m16n8k16.row.col.f32.bf16.bf16.f32 "
                 "{%0,%1,%2,%3},{%4,%5,%6,%7},{%8,%9},{%10,%10,%10,%10};"
                 : "=f"(d[0]), "=f"(d[1]), "=f"(d[2]), "=f"(d[3])
                 : "r"(a0), "r"(a1), "r"(a2), "r"(a3), "r"(b0), "r"(b1), "f"(0.0f));
}

// ---------------------------------------------------------------------------
// Kernel 1: prep — grid 8 x 256.
// ---------------------------------------------------------------------------
__global__ void __launch_bounds__(256) hmm_prep_kernel(
        const float* __restrict__ sp, const float* __restrict__ trans,
        const float* __restrict__ mu, const float* __restrict__ log_var) {
    cudaTriggerProgrammaticLaunchCompletion();
    int tid = threadIdx.x, wid = tid >> 5, lane = tid & 31;
    int gw = blockIdx.x * 8 + wid;

    if (gw < 32) {
        float v = trans[gw * KK + lane];
        float m = warpMax(v);
        float e = expf(v - m);
        float s = warpSum(e);
        g_expA[gw * KK + lane] = e / s;
        if (gw == 0) {
            float pv = sp[lane];
            float pm = warpMax(pv);
            float pe = expf(pv - pm);
            float ps = warpSum(pe);
            g_pi[lane] = pe / ps;
        }
    } else {
        int k = gw - 32;
        float acc = 0.0f;
        for (int d = lane; d < DD; d += 32) {
            float lv = log_var[k * DD + d];
            float iv = expf(-lv);
            float m = mu[k * DD + d];
            acc = fmaf(m * m, iv, acc + lv);
        }
        acc = warpSum(acc);
        if (lane == 0) g_bias[k] = -0.5f * (acc + (float)DD * LOG2PI_F);
    }

    int p = blockIdx.x * 256 + tid;
    if (p < 12 * 4 * 32) {
        int s = p >> 7;
        int rem = p & 127;
        int ln = rem & 31;
        int gid = ln >> 2, tig = ln & 3;
        int n = (rem >> 5) * 8 + gid;
        float w[4];
#pragma unroll
        for (int h = 0; h < 4; ++h) {
            int row = s * 16 + tig * 2 + (h >> 1) * 8 + (h & 1);
            float v = 0.f;
            if (row < 96) {
                int d = row;
                if (d < DD) v = mu[n * DD + d] * expf(-log_var[n * DD + d]);
            } else {
                int d = row - 96;
                if (d < DD) v = -0.5f * expf(-log_var[n * DD + d]);
            }
            w[h] = v;
        }
        g_Wb[p] = make_uint2(packbf2(w[0], w[1]), packbf2(w[2], w[3]));
    }
}

// ---------------------------------------------------------------------------
// Kernel 2: emissions (bf16 MMA). X staged in smem AS BF16 (23 KB).
// ---------------------------------------------------------------------------
__global__ void __launch_bounds__(256) hmm_emis_kernel(const float* __restrict__ X) {
    cudaTriggerProgrammaticLaunchCompletion();
    __shared__ __align__(16) uint32_t xsb[128 * 45];   // 23.04 KB
    __shared__ __align__(16) uint2 ws[12 * 4 * 32];    // 12 KB
    __shared__ __align__(8) float sbias[KK];
    __shared__ float mred[8];

    int tid = threadIdx.x;
    int wid = tid >> 5, lane = tid & 31;
    int gid = lane >> 2, tig = lane & 3;

    {   // stage X tile (f32 -> bf16x2 on the fly) — independent of prep
        const float4* X4 = (const float4*)(X + (long)blockIdx.x * 128 * DD);
        uint2* xs2 = (uint2*)xsb;
#pragma unroll
        for (int i = 0; i < 11; ++i) {
            float4 v = X4[tid + 256 * i];
            xs2[tid + 256 * i] = make_uint2(packbf2(v.x, v.y), packbf2(v.z, v.w));
        }
        if (tid < 2880 - 2816) {
            float4 v = X4[tid + 2816];
            xs2[tid + 2816] = make_uint2(packbf2(v.x, v.y), packbf2(v.z, v.w));
        }
    }
    cudaGridDependencySynchronize();     // wait for prep's g_Wb / g_bias
    {
        const uint4* src = (const uint4*)g_Wb;
        uint4* dst = (uint4*)ws;
#pragma unroll
        for (int i = 0; i < 3; ++i) dst[tid + 256 * i] = src[tid + 256 * i];
        if (tid < KK) sbias[tid] = g_bias[tid];
    }
    __syncthreads();

    const uint32_t* xr0 = xsb + (wid * 16 + gid) * 45;
    const uint32_t* xr1 = xr0 + 8 * 45;

    float acc[4][4];
#pragma unroll
    for (int nt = 0; nt < 4; ++nt)
#pragma unroll
        for (int i = 0; i < 4; ++i) acc[nt][i] = 0.f;

#pragma unroll
    for (int s = 0; s < 6; ++s) {
        int w0 = s * 8 + tig;
        int w1 = w0 + 4;
        bool v1 = (s * 16 + tig * 2 + 8) < DD;
        uint32_t a0 = xr0[w0];
        uint32_t a1 = xr1[w0];
        uint32_t a2 = v1 ? xr0[w1] : 0u;
        uint32_t a3 = v1 ? xr1[w1] : 0u;
        uint32_t q0 = sqbf2(a0), q1 = sqbf2(a1), q2 = sqbf2(a2), q3 = sqbf2(a3);
#pragma unroll
        for (int nt = 0; nt < 4; ++nt) {
            uint2 bb = ws[(s * 4 + nt) * 32 + lane];
            mma_bf16(acc[nt][0], acc[nt][1], acc[nt][2], acc[nt][3],
                     a0, a1, a2, a3, bb.x, bb.y);
        }
#pragma unroll
        for (int nt = 0; nt < 4; ++nt) {
            uint2 bb = ws[((s + 6) * 4 + nt) * 32 + lane];
            mma_bf16(acc[nt][0], acc[nt][1], acc[nt][2], acc[nt][3],
                     q0, q1, q2, q3, bb.x, bb.y);
        }
    }

    const float2* sb2 = (const float2*)sbias;
    float m0 = -1e30f, m1 = -1e30f;
#pragma unroll
    for (int nt = 0; nt < 4; ++nt) {
        float2 bv = sb2[nt * 4 + tig];
        acc[nt][0] += bv.x; acc[nt][1] += bv.y;
        acc[nt][2] += bv.x; acc[nt][3] += bv.y;
        m0 = fmaxf(m0, fmaxf(acc[nt][0], acc[nt][1]));
        m1 = fmaxf(m1, fmaxf(acc[nt][2], acc[nt][3]));
    }
#pragma unroll
    for (int o = 1; o <= 2; o <<= 1) {
        m0 = fmaxf(m0, __shfl_xor_sync(FULLMASK, m0, o));
        m1 = fmaxf(m1, __shfl_xor_sync(FULLMASK, m1, o));
    }
    long r0 = (long)(blockIdx.x >> 5) * ERows + PADF
            + (blockIdx.x & 31) * 128 + wid * 16 + gid;
    long r1 = r0 + 8;
    uint4 o0, o1;
    o0.x = packbf2(__expf(acc[0][0] - m0), __expf(acc[0][1] - m0));
    o0.y = packbf2(__expf(acc[1][0] - m0), __expf(acc[1][1] - m0));
    o0.z = packbf2(__expf(acc[2][0] - m0), __expf(acc[2][1] - m0));
    o0.w = packbf2(__expf(acc[3][0] - m0), __expf(acc[3][1] - m0));
    o1.x = packbf2(__expf(acc[0][2] - m1), __expf(acc[0][3] - m1));
    o1.y = packbf2(__expf(acc[1][2] - m1), __expf(acc[1][3] - m1));
    o1.z = packbf2(__expf(acc[2][2] - m1), __expf(acc[2][3] - m1));
    o1.w = packbf2(__expf(acc[3][2] - m1), __expf(acc[3][3] - m1));
    ((uint4*)(g_ee16 + r0 * KK))[tig] = o0;
    ((uint4*)(g_ee16 + r1 * KK))[tig] = o1;

    float msum = (tig == 0) ? (m0 + m1) : 0.f;
    msum = warpSum(msum);
    if (lane == 0) mred[wid] = msum;
    __syncthreads();
    if (tid == 0) {
        float s = 0.f;
#pragma unroll
        for (int i = 0; i < 8; ++i) s += mred[i];
        g_emaxpart[blockIdx.x] = s;
    }
}

// ---------------------------------------------------------------------------
// Kernel 3: tensor-core chunked scan, CC=256, NSTEP=24, gridsync on emission.
// (final reduction deliberately NOT fused — R7/R13 register-pressure lesson)
// ---------------------------------------------------------------------------
__global__ void __launch_bounds__(128) hmm_scan_kernel() {
    cudaTriggerProgrammaticLaunchCompletion();
    cudaGridDependencySynchronize();     // wait for emission (and transitively prep)
    int wid = threadIdx.x >> 5;
    int w = blockIdx.x * 4 + wid;        // 0..1023
    int lane = threadIdx.x & 31;
    int gid = lane >> 2, tig = lane & 3;
    int b = w >> 4;                      // 16 warps per batch
    int g = w & 15;
    int c0 = g * 16 + gid;               // 0..247
    int c1 = c0 + 8;                     // 8..255
    const __nv_bfloat16* eb = g_ee16 + (long)b * (ERows * KK);

    uint32_t Bf[8][2];
#pragma unroll
    for (int ks = 0; ks < 2; ++ks)
#pragma unroll
        for (int nt = 0; nt < 4; ++nt) {
            int n = nt * 8 + gid;
            int r = ks * 16 + 2 * tig;
            Bf[ks * 4 + nt][0] = packbf2(g_expA[r * KK + n], g_expA[(r + 1) * KK + n]);
            Bf[ks * 4 + nt][1] = packbf2(g_expA[(r + 8) * KK + n], g_expA[(r + 9) * KK + n]);
        }

    uint32_t pk[4][2];
    {
        uint4 ei = ((const uint4*)(eb + (long)PADF * KK))[tig];
        uint32_t ec[4] = {ei.x, ei.y, ei.z, ei.w};
#pragma unroll
        for (int nt = 0; nt < 4; ++nt) {
            float i00 = 1.f, i01 = 1.f;
            if (c0 == 0) {
                float2 ef = __bfloat1622float2(bfu(ec[nt]));
                i00 = g_pi[nt * 8 + 2 * tig] * ef.x;
                i01 = g_pi[nt * 8 + 2 * tig + 1] * ef.y;
            }
            pk[nt][0] = packbf2(i00, i01);
            pk[nt][1] = packbf2(1.f, 1.f);
        }
    }

    int ilo0 = (c0 == 0) ? WARM : 0;
    int ihi1 = (c1 == CC - 1) ? (NSTEP - 1) : NSTEP;

    const __nv_bfloat16* pe0 = eb + (long)(c0 * CHUNK + 1) * KK;
    const __nv_bfloat16* pe1 = eb + (long)(c1 * CHUNK + 1) * KK;

    uint4 ring0[4], ring1[4];
#pragma unroll
    for (int s = 0; s < 4; ++s) {
        ring0[s] = ((const uint4*)(pe0 + (long)s * KK))[tig];
        ring1[s] = ((const uint4*)(pe1 + (long)s * KK))[tig];
    }

    float logZ0 = 0.f, logZ1 = 0.f;
    for (int blk = 0; blk < NSTEP / 8; ++blk) {      // 3 blocks
        const __nv_bfloat16* q0 = pe0 + (long)(blk * 8 + 4) * KK;
        const __nv_bfloat16* q1 = pe1 + (long)(blk * 8 + 4) * KK;
        bool doLog = (blk >= WARM / 8);
#pragma unroll
        for (int ii = 0; ii < 8; ++ii) {
            int i = blk * 8 + ii;
            float dA[4][4], dB[4][4];
#pragma unroll
            for (int nt = 0; nt < 4; ++nt)
                mma_bf16_z(dA[nt], pk[0][0], pk[0][1], pk[1][0], pk[1][1],
                           Bf[nt][0], Bf[nt][1]);
#pragma unroll
            for (int nt = 0; nt < 4; ++nt)
                mma_bf16_z(dB[nt], pk[2][0], pk[2][1], pk[3][0], pk[3][1],
                           Bf[4 + nt][0], Bf[4 + nt][1]);

            const int slot = ii & 3;
            uint4 e0 = ring0[slot], e1 = ring1[slot];
            ring0[slot] = ((const uint4*)(q0 + (long)ii * KK))[tig];
            ring1[slot] = ((const uint4*)(q1 + (long)ii * KK))[tig];
            uint32_t ec0[4] = {e0.x, e0.y, e0.z, e0.w};
            uint32_t ec1[4] = {e1.x, e1.y, e1.z, e1.w};

            __nv_bfloat162 n0[4], n1[4];
#pragma unroll
            for (int nt = 0; nt < 4; ++nt) {
                __nv_bfloat162 d0 = __floats2bfloat162_rn(dA[nt][0] + dB[nt][0],
                                                          dA[nt][1] + dB[nt][1]);
                __nv_bfloat162 d1 = __floats2bfloat162_rn(dA[nt][2] + dB[nt][2],
                                                          dA[nt][3] + dB[nt][3]);
                n0[nt] = __hmul2(d0, bfu(ec0[nt]));
                n1[nt] = __hmul2(d1, bfu(ec1[nt]));
            }

            bool val0 = (i >= ilo0);
            bool val1 = (i < ihi1);
            if (ii == 7) {
                float S0 = 0.f, S1 = 0.f;
#pragma unroll
                for (int nt = 0; nt < 4; ++nt) {
                    float2 a = __bfloat1622float2(n0[nt]);
                    float2 c = __bfloat1622float2(n1[nt]);
                    S0 += a.x + a.y;
                    S1 += c.x + c.y;
                }
#pragma unroll
                for (int o = 1; o <= 2; o <<= 1) {
                    S0 += __shfl_xor_sync(FULLMASK, S0, o);
                    S1 += __shfl_xor_sync(FULLMASK, S1, o);
                }
                bool ren0 = val0 && (doLog || c0 != 0);
                bool ren1 = val1;
                float sc0 = ren0 ? __frcp_rn(S0) : 1.f;
                float sc1 = ren1 ? __frcp_rn(S1) : 1.f;
                if (doLog && val0) logZ0 += __logf(S0);
                if (doLog && val1) logZ1 += __logf(S1);
                __nv_bfloat162 sb0 = __float2bfloat162_rn(sc0);
                __nv_bfloat162 sb1 = __float2bfloat162_rn(sc1);
#pragma unroll
                for (int nt = 0; nt < 4; ++nt) {
                    n0[nt] = __hmul2(n0[nt], sb0);
                    n1[nt] = __hmul2(n1[nt], sb1);
                }
            }
#pragma unroll
            for (int nt = 0; nt < 4; ++nt) {
                pk[nt][0] = val0 ? ubf(n0[nt]) : pk[nt][0];
                pk[nt][1] = val1 ? ubf(n1[nt]) : pk[nt][1];
            }
        }
    }

    float S0 = 0.f, S1 = 0.f;
#pragma unroll
    for (int nt = 0; nt < 4; ++nt) {
        float2 a = __bfloat1622float2(bfu(pk[nt][0]));
        float2 c = __bfloat1622float2(bfu(pk[nt][1]));
        S0 += a.x + a.y;
        S1 += c.x + c.y;
    }
#pragma unroll
    for (int o = 1; o <= 2; o <<= 1) {
        S0 += __shfl_xor_sync(FULLMASK, S0, o);
        S1 += __shfl_xor_sync(FULLMASK, S1, o);
    }
    if (tig == 0) {
        g_partial2[b * CC + c0] = logZ0 + __logf(S0);
        g_partial2[b * CC + c1] = logZ1 + __logf(S1);
    }
}

// ---------------------------------------------------------------------------
// Kernel 4: final scalar (deterministic fixed-order double reduction)
// ---------------------------------------------------------------------------
__global__ void __launch_bounds__(256) hmm_final_kernel(float* __restrict__ out) {
    cudaGridDependencySynchronize();
    __shared__ double red[8];
    int tid = threadIdx.x;
    double v = 0.0;
    const float4* p2 = (const float4*)g_partial2;
    const float4* pe = (const float4*)g_emaxpart;
#pragma unroll
    for (int i = tid; i < BB * CC / 4; i += 256) {
        float4 a = p2[i];
        v += (double)a.x + (double)a.y + (double)a.z + (double)a.w;
    }
#pragma unroll
    for (int i = tid; i < NEB / 4; i += 256) {
        float4 a = pe[i];
        v += (double)a.x + (double)a.y + (double)a.z + (double)a.w;
    }
#pragma unroll
    for (int o = 16; o > 0; o >>= 1) v += __shfl_xor_sync(FULLMASK, v, o);
    if ((tid & 31) == 0) red[tid >> 5] = v;
    __syncthreads();
    if (tid < 8) {
        double wv = red[tid];
#pragma unroll
        for (int o = 4; o > 0; o >>= 1) wv += __shfl_xor_sync(0xff, wv, o);
        if (tid == 0) out[0] = (float)wv;
    }
}

// ---------------------------------------------------------------------------
extern "C" void kernel_launch(void* const* d_in, const int* in_sizes, int n_in,
                              void* d_out, int out_size) {
    const float* X = (const float*)d_in[0];
    const float* sp = (const float*)d_in[1];
    const float* trans = (const float*)d_in[2];
    const float* mu = (const float*)d_in[3];
    const float* log_var = (const float*)d_in[4];

    hmm_prep_kernel<<<8, 256>>>(sp, trans, mu, log_var);

    cudaLaunchAttribute at[1];
    at[0].id = cudaLaunchAttributeProgrammaticStreamSerialization;
    at[0].val.programmaticStreamSerializationAllowed = 1;

    cudaLaunchConfig_t cfg = {};
    cfg.attrs = at;
    cfg.numAttrs = 1;
    cfg.stream = 0;

    cfg.gridDim = dim3(NEB);
    cfg.blockDim = dim3(256);
    cudaLaunchKernelEx(&cfg, hmm_emis_kernel, X);

    cfg.gridDim = dim3(NSB);             // 256 blocks x 4 warps
    cfg.blockDim = dim3(128);
    cudaLaunchKernelEx(&cfg, hmm_scan_kernel);

    cfg.gridDim = dim3(1);
    cfg.blockDim = dim3(256);
    float* outp = (float*)d_out;
    cudaLaunchKernelEx(&cfg, hmm_final_kernel, outp);
}

// round 15
// speedup vs baseline: 1.0423x; 1.0054x over previous
#include <cuda_runtime.h>
#include <cuda_bf16.h>
#include <math.h>
#include <stdint.h>

#define BB 64
#define TT 4096
#define DD 90
#define KK 32
#define CC 128           // chunks per batch (R12-validated)
#define CHUNK 32         // TT / CC
#define WARM 8           // burn-in steps
#define NSTEP (WARM + CHUNK)     // 40
#define PADF 8           // MUST == WARM
#define PADB 8
#define ERows (PADF + TT + PADB) // 4112 rows per batch
#define NEB (BB * TT / 128)      // 2048 emission tiles
#define GB 296                   // persistent grid (2/SM on 148 SMs)
#define LOG2PI_F 1.8378770664093453f
#define FULLMASK 0xffffffffu

// ---- scratch (__device__ globals; no allocations allowed) ----
__device__ __align__(16) __nv_bfloat16 g_ee16[BB * ERows * KK];
__device__ __align__(16) uint2 g_Wb[12 * 4 * 32];
__device__ __align__(16) float g_bias[KK];
__device__ float g_pi[KK];
__device__ float g_expA[KK * KK];
__device__ __align__(16) float g_partial2[BB * CC];
__device__ __align__(16) float g_emaxpart[NEB];
__device__ unsigned g_cnt1, g_flag1, g_cnt2;   // grid-barrier state (self-resetting)

__device__ __forceinline__ float warpMax(float v) {
#pragma unroll
    for (int o = 16; o > 0; o >>= 1) v = fmaxf(v, __shfl_xor_sync(FULLMASK, v, o));
    return v;
}
__device__ __forceinline__ float warpSum(float v) {
#pragma unroll
    for (int o = 16; o > 0; o >>= 1) v += __shfl_xor_sync(FULLMASK, v, o);
    return v;
}
__device__ __forceinline__ uint32_t packbf2(float lo, float hi) {
    __nv_bfloat162 h = __floats2bfloat162_rn(lo, hi);
    return *reinterpret_cast<uint32_t*>(&h);
}
__device__ __forceinline__ __nv_bfloat162 bfu(uint32_t v) {
    return *reinterpret_cast<__nv_bfloat162*>(&v);
}
__device__ __forceinline__ uint32_t ubf(__nv_bfloat162 h) {
    return *reinterpret_cast<uint32_t*>(&h);
}
__device__ __forceinline__ uint32_t sqbf2(uint32_t v) {
    float2 f = __bfloat1622float2(bfu(v));
    return packbf2(f.x * f.x, f.y * f.y);
}
__device__ __forceinline__ void mma_bf16(float& d0, float& d1, float& d2, float& d3,
                                         uint32_t a0, uint32_t a1, uint32_t a2, uint32_t a3,
                                         uint32_t b0, uint32_t b1) {
    asm volatile("mma.sync.aligned.m16n8k16.row.col.f32.bf16.bf16.f32 "
                 "{%0,%1,%2,%3},{%4,%5,%6,%7},{%8,%9},{%0,%1,%2,%3};"
                 : "+f"(d0), "+f"(d1), "+f"(d2), "+f"(d3)
                 : "r"(a0), "r"(a1), "r"(a2), "r"(a3), "r"(b0), "r"(b1));
}
__device__ __forceinline__ void mma_bf16_z(float* d,
                                           uint32_t a0, uint32_t a1, uint32_t a2, uint32_t a3,
                                           uint32_t b0, uint32_t b1) {
    asm volatile("mma.sync.aligned.m16n8k16.row.col.f32.bf16.bf16.f32 "
                 "{%0,%1,%2,%3},{%4,%5,%6,%7},{%8,%9},{%10,%10,%10,%10};"
                 : "=f"(d[0]), "=f"(d[1]), "=f"(d[2]), "=f"(d[3])
                 : "r"(a0), "r"(a1), "r"(a2), "r"(a3), "r"(b0), "r"(b1), "f"(0.0f));
}

// ---------------------------------------------------------------------------
// Kernel 1: prep — grid 8 x 256 (unchanged from R12).
// ---------------------------------------------------------------------------
__global__ void __launch_bounds__(256) hmm_prep_kernel(
        const float* __restrict__ sp, const float* __restrict__ trans,
        const float* __restrict__ mu, const float* __restrict__ log_var) {
    cudaTriggerProgrammaticLaunchCompletion();
    int tid = threadIdx.x, wid = tid >> 5, lane = tid & 31;
    int gw = blockIdx.x * 8 + wid;

    if (gw < 32) {
        float v = trans[gw * KK + lane];
        float m = warpMax(v);
        float e = expf(v - m);
        float s = warpSum(e);
        g_expA[gw * KK + lane] = e / s;
        if (gw == 0) {
            float pv = sp[lane];
            float pm = warpMax(pv);
            float pe = expf(pv - pm);
            float ps = warpSum(pe);
            g_pi[lane] = pe / ps;
        }
    } else {
        int k = gw - 32;
        float acc = 0.0f;
        for (int d = lane; d < DD; d += 32) {
            float lv = log_var[k * DD + d];
            float iv = expf(-lv);
            float m = mu[k * DD + d];
            acc = fmaf(m * m, iv, acc + lv);
        }
        acc = warpSum(acc);
        if (lane == 0) g_bias[k] = -0.5f * (acc + (float)DD * LOG2PI_F);
    }

    int p = blockIdx.x * 256 + tid;
    if (p < 12 * 4 * 32) {
        int s = p >> 7;
        int rem = p & 127;
        int ln = rem & 31;
        int gid = ln >> 2, tig = ln & 3;
        int n = (rem >> 5) * 8 + gid;
        float w[4];
#pragma unroll
        for (int h = 0; h < 4; ++h) {
            int row = s * 16 + tig * 2 + (h >> 1) * 8 + (h & 1);
            float v = 0.f;
            if (row < 96) {
                int d = row;
                if (d < DD) v = mu[n * DD + d] * expf(-log_var[n * DD + d]);
            } else {
                int d = row - 96;
                if (d < DD) v = -0.5f * expf(-log_var[n * DD + d]);
            }
            w[h] = v;
        }
        g_Wb[p] = make_uint2(packbf2(w[0], w[1]), packbf2(w[2], w[3]));
    }
}

__device__ __forceinline__ void stage_x_tile(uint32_t* xsb, const float* __restrict__ X,
                                             int tile, int tid) {
    const float4* X4 = (const float4*)(X + (long)tile * 128 * DD);
    uint2* xs2 = (uint2*)xsb;
#pragma unroll
    for (int i = 0; i < 11; ++i) {
        float4 v = X4[tid + 256 * i];
        xs2[tid + 256 * i] = make_uint2(packbf2(v.x, v.y), packbf2(v.z, v.w));
    }
    if (tid < 64) {
        float4 v = X4[tid + 2816];
        xs2[tid + 2816] = make_uint2(packbf2(v.x, v.y), packbf2(v.z, v.w));
    }
}

// ---------------------------------------------------------------------------
// Kernel 2: FUSED persistent emission + scan + final. 296 blocks x 256 thr.
// Phase 1: each block loops over emission tiles (R12 body).
// Grid barrier 1 (full, epoch-based). Phase 2: blocks 0..63 run the R12 scan
// (512 warps). Barrier 2 (only block 0 waits). Block 0: fixed-order reduction.
// ---------------------------------------------------------------------------
__global__ void __launch_bounds__(256, 2) hmm_fused_kernel(
        const float* __restrict__ X, float* __restrict__ out) {
    __shared__ __align__(16) uint32_t xsb[128 * 45];   // 23.04 KB
    __shared__ __align__(16) uint2 ws[12 * 4 * 32];    // 12 KB
    __shared__ __align__(8) float sbias[KK];
    __shared__ float mred[8];
    __shared__ double red[8];

    int tid = threadIdx.x;
    int wid = tid >> 5, lane = tid & 31;
    int gid = lane >> 2, tig = lane & 3;

    // ---------------- Phase 1: emission ----------------
    int tile = blockIdx.x;
    stage_x_tile(xsb, X, tile, tid);      // overlaps prep via PDL
    cudaGridDependencySynchronize();      // wait for prep outputs
    {
        const uint4* src = (const uint4*)g_Wb;
        uint4* dst = (uint4*)ws;
#pragma unroll
        for (int i = 0; i < 3; ++i) dst[tid + 256 * i] = src[tid + 256 * i];
        if (tid < KK) sbias[tid] = g_bias[tid];
    }
    __syncthreads();

    while (tile < NEB) {
        const uint32_t* xr0 = xsb + (wid * 16 + gid) * 45;
        const uint32_t* xr1 = xr0 + 8 * 45;

        float acc[4][4];
#pragma unroll
        for (int nt = 0; nt < 4; ++nt)
#pragma unroll
            for (int i = 0; i < 4; ++i) acc[nt][i] = 0.f;

#pragma unroll
        for (int s = 0; s < 6; ++s) {
            int w0 = s * 8 + tig;
            int w1 = w0 + 4;
            bool v1 = (s * 16 + tig * 2 + 8) < DD;
            uint32_t a0 = xr0[w0];
            uint32_t a1 = xr1[w0];
            uint32_t a2 = v1 ? xr0[w1] : 0u;
            uint32_t a3 = v1 ? xr1[w1] : 0u;
            uint32_t q0 = sqbf2(a0), q1 = sqbf2(a1), q2 = sqbf2(a2), q3 = sqbf2(a3);
#pragma unroll
            for (int nt = 0; nt < 4; ++nt) {
                uint2 bb = ws[(s * 4 + nt) * 32 + lane];
                mma_bf16(acc[nt][0], acc[nt][1], acc[nt][2], acc[nt][3],
                         a0, a1, a2, a3, bb.x, bb.y);
            }
#pragma unroll
            for (int nt = 0; nt < 4; ++nt) {
                uint2 bb = ws[((s + 6) * 4 + nt) * 32 + lane];
                mma_bf16(acc[nt][0], acc[nt][1], acc[nt][2], acc[nt][3],
                         q0, q1, q2, q3, bb.x, bb.y);
            }
        }

        const float2* sb2 = (const float2*)sbias;
        float m0 = -1e30f, m1 = -1e30f;
#pragma unroll
        for (int nt = 0; nt < 4; ++nt) {
            float2 bv = sb2[nt * 4 + tig];
            acc[nt][0] += bv.x; acc[nt][1] += bv.y;
            acc[nt][2] += bv.x; acc[nt][3] += bv.y;
            m0 = fmaxf(m0, fmaxf(acc[nt][0], acc[nt][1]));
            m1 = fmaxf(m1, fmaxf(acc[nt][2], acc[nt][3]));
        }
#pragma unroll
        for (int o = 1; o <= 2; o <<= 1) {
            m0 = fmaxf(m0, __shfl_xor_sync(FULLMASK, m0, o));
            m1 = fmaxf(m1, __shfl_xor_sync(FULLMASK, m1, o));
        }
        long r0 = (long)(tile >> 5) * ERows + PADF
                + (tile & 31) * 128 + wid * 16 + gid;
        long r1 = r0 + 8;
        uint4 o0, o1;
        o0.x = packbf2(__expf(acc[0][0] - m0), __expf(acc[0][1] - m0));
        o0.y = packbf2(__expf(acc[1][0] - m0), __expf(acc[1][1] - m0));
        o0.z = packbf2(__expf(acc[2][0] - m0), __expf(acc[2][1] - m0));
        o0.w = packbf2(__expf(acc[3][0] - m0), __expf(acc[3][1] - m0));
        o1.x = packbf2(__expf(acc[0][2] - m1), __expf(acc[0][3] - m1));
        o1.y = packbf2(__expf(acc[1][2] - m1), __expf(acc[1][3] - m1));
        o1.z = packbf2(__expf(acc[2][2] - m1), __expf(acc[2][3] - m1));
        o1.w = packbf2(__expf(acc[3][2] - m1), __expf(acc[3][3] - m1));
        ((uint4*)(g_ee16 + r0 * KK))[tig] = o0;
        ((uint4*)(g_ee16 + r1 * KK))[tig] = o1;

        float msum = (tig == 0) ? (m0 + m1) : 0.f;
        msum = warpSum(msum);
        if (lane == 0) mred[wid] = msum;
        __syncthreads();                       // xsb reads done + mred ready
        if (tid == 0) {
            float s = 0.f;
#pragma unroll
            for (int i = 0; i < 8; ++i) s += mred[i];
            g_emaxpart[tile] = s;
        }
        int next = tile + GB;
        if (next < NEB) stage_x_tile(xsb, X, next, tid);
        __syncthreads();
        tile = next;
    }

    // ---------------- Grid barrier 1 (full) ----------------
    __threadfence();
    __syncthreads();
    if (tid == 0) {
        unsigned epoch = atomicAdd(&g_flag1, 0u);
        unsigned old = atomicAdd(&g_cnt1, 1u);
        if (old == GB - 1) {
            atomicExch(&g_cnt1, 0u);
            __threadfence();
            atomicAdd(&g_flag1, 1u);
        } else {
            while (atomicAdd(&g_flag1, 0u) == epoch) __nanosleep(64);
        }
    }
    __syncthreads();
    __threadfence();

    // ---------------- Phase 2: scan (blocks 0..63, 512 warps) ----------------
    if (blockIdx.x < 64) {
        int w = blockIdx.x * 8 + wid;        // 0..511
        int b = w >> 3;                      // 8 warps per batch
        int g = w & 7;
        int c0 = g * 16 + gid;               // 0..119
        int c1 = c0 + 8;                     // 8..127
        const __nv_bfloat16* eb = g_ee16 + (long)b * (ERows * KK);

        uint32_t Bf[8][2];
#pragma unroll
        for (int ks = 0; ks < 2; ++ks)
#pragma unroll
            for (int nt = 0; nt < 4; ++nt) {
                int n = nt * 8 + gid;
                int r = ks * 16 + 2 * tig;
                Bf[ks * 4 + nt][0] = packbf2(g_expA[r * KK + n], g_expA[(r + 1) * KK + n]);
                Bf[ks * 4 + nt][1] = packbf2(g_expA[(r + 8) * KK + n], g_expA[(r + 9) * KK + n]);
            }

        uint32_t pk[4][2];
        {
            uint4 ei = ((const uint4*)(eb + (long)PADF * KK))[tig];
            uint32_t ec[4] = {ei.x, ei.y, ei.z, ei.w};
#pragma unroll
            for (int nt = 0; nt < 4; ++nt) {
                float i00 = 1.f, i01 = 1.f;
                if (c0 == 0) {
                    float2 ef = __bfloat1622float2(bfu(ec[nt]));
                    i00 = g_pi[nt * 8 + 2 * tig] * ef.x;
                    i01 = g_pi[nt * 8 + 2 * tig + 1] * ef.y;
                }
                pk[nt][0] = packbf2(i00, i01);
                pk[nt][1] = packbf2(1.f, 1.f);
            }
        }

        int ilo0 = (c0 == 0) ? WARM : 0;
        int ihi1 = (c1 == CC - 1) ? (NSTEP - 1) : NSTEP;

        const __nv_bfloat16* pe0 = eb + (long)(c0 * CHUNK + 1) * KK;
        const __nv_bfloat16* pe1 = eb + (long)(c1 * CHUNK + 1) * KK;

        uint4 ring0[4], ring1[4];
#pragma unroll
        for (int s = 0; s < 4; ++s) {
            ring0[s] = ((const uint4*)(pe0 + (long)s * KK))[tig];
            ring1[s] = ((const uint4*)(pe1 + (long)s * KK))[tig];
        }

        float logZ0 = 0.f, logZ1 = 0.f;
        for (int blk = 0; blk < NSTEP / 8; ++blk) {      // 5 blocks
            const __nv_bfloat16* q0 = pe0 + (long)(blk * 8 + 4) * KK;
            const __nv_bfloat16* q1 = pe1 + (long)(blk * 8 + 4) * KK;
            bool doLog = (blk >= WARM / 8);
#pragma unroll
            for (int ii = 0; ii < 8; ++ii) {
                int i = blk * 8 + ii;
                float dA[4][4], dB[4][4];
#pragma unroll
                for (int nt = 0; nt < 4; ++nt)
                    mma_bf16_z(dA[nt], pk[0][0], pk[0][1], pk[1][0], pk[1][1],
                               Bf[nt][0], Bf[nt][1]);
#pragma unroll
                for (int nt = 0; nt < 4; ++nt)
                    mma_bf16_z(dB[nt], pk[2][0], pk[2][1], pk[3][0], pk[3][1],
                               Bf[4 + nt][0], Bf[4 + nt][1]);

                const int slot = ii & 3;
                uint4 e0 = ring0[slot], e1 = ring1[slot];
                ring0[slot] = ((const uint4*)(q0 + (long)ii * KK))[tig];
                ring1[slot] = ((const uint4*)(q1 + (long)ii * KK))[tig];
                uint32_t ec0[4] = {e0.x, e0.y, e0.z, e0.w};
                uint32_t ec1[4] = {e1.x, e1.y, e1.z, e1.w};

                __nv_bfloat162 n0[4], n1[4];
#pragma unroll
                for (int nt = 0; nt < 4; ++nt) {
                    __nv_bfloat162 d0 = __floats2bfloat162_rn(dA[nt][0] + dB[nt][0],
                                                              dA[nt][1] + dB[nt][1]);
                    __nv_bfloat162 d1 = __floats2bfloat162_rn(dA[nt][2] + dB[nt][2],
                                                              dA[nt][3] + dB[nt][3]);
                    n0[nt] = __hmul2(d0, bfu(ec0[nt]));
                    n1[nt] = __hmul2(d1, bfu(ec1[nt]));
                }

                bool val0 = (i >= ilo0);
                bool val1 = (i < ihi1);
                if (ii == 7) {
                    float S0 = 0.f, S1 = 0.f;
#pragma unroll
                    for (int nt = 0; nt < 4; ++nt) {
                        float2 a = __bfloat1622float2(n0[nt]);
                        float2 c = __bfloat1622float2(n1[nt]);
                        S0 += a.x + a.y;
                        S1 += c.x + c.y;
                    }
#pragma unroll
                    for (int o = 1; o <= 2; o <<= 1) {
                        S0 += __shfl_xor_sync(FULLMASK, S0, o);
                        S1 += __shfl_xor_sync(FULLMASK, S1, o);
                    }
                    bool ren0 = val0 && (doLog || c0 != 0);
                    bool ren1 = val1;
                    float sc0 = ren0 ? __frcp_rn(S0) : 1.f;
                    float sc1 = ren1 ? __frcp_rn(S1) : 1.f;
                    if (doLog && val0) logZ0 += __logf(S0);
                    if (doLog && val1) logZ1 += __logf(S1);
                    __nv_bfloat162 sb0 = __float2bfloat162_rn(sc0);
                    __nv_bfloat162 sb1 = __float2bfloat162_rn(sc1);
#pragma unroll
                    for (int nt = 0; nt < 4; ++nt) {
                        n0[nt] = __hmul2(n0[nt], sb0);
                        n1[nt] = __hmul2(n1[nt], sb1);
                    }
                }
#pragma unroll
                for (int nt = 0; nt < 4; ++nt) {
                    pk[nt][0] = val0 ? ubf(n0[nt]) : pk[nt][0];
                    pk[nt][1] = val1 ? ubf(n1[nt]) : pk[nt][1];
                }
            }
        }

        float S0 = 0.f, S1 = 0.f;
#pragma unroll
        for (int nt = 0; nt < 4; ++nt) {
            float2 a = __bfloat1622float2(bfu(pk[nt][0]));
            float2 c = __bfloat1622float2(bfu(pk[nt][1]));
            S0 += a.x + a.y;
            S1 += c.x + c.y;
        }
#pragma unroll
        for (int o = 1; o <= 2; o <<= 1) {
            S0 += __shfl_xor_sync(FULLMASK, S0, o);
            S1 += __shfl_xor_sync(FULLMASK, S1, o);
        }
        if (tig == 0) {
            g_partial2[b * CC + c0] = logZ0 + __logf(S0);
            g_partial2[b * CC + c1] = logZ1 + __logf(S1);
        }
    }

    // ---------------- Barrier 2 + final (block 0 only waits) ----------------
    __threadfence();
    __syncthreads();
    if (blockIdx.x != 0) {
        if (tid == 0) atomicAdd(&g_cnt2, 1u);
        return;
    }
    if (tid == 0) {
        while (atomicAdd(&g_cnt2, 0u) < GB - 1) __nanosleep(64);
        atomicExch(&g_cnt2, 0u);
    }
    __syncthreads();
    __threadfence();

    double v = 0.0;
    const float4* p2 = (const float4*)g_partial2;
    const float4* pe = (const float4*)g_emaxpart;
    for (int i = tid; i < BB * CC / 4; i += 256) {
        float4 a = p2[i];
        v += (double)a.x + (double)a.y + (double)a.z + (double)a.w;
    }
    for (int i = tid; i < NEB / 4; i += 256) {
        float4 a = pe[i];
        v += (double)a.x + (double)a.y + (double)a.z + (double)a.w;
    }
#pragma unroll
    for (int o = 16; o > 0; o >>= 1) v += __shfl_xor_sync(FULLMASK, v, o);
    if ((tid & 31) == 0) red[tid >> 5] = v;
    __syncthreads();
    if (tid < 8) {
        double wv = red[tid];
#pragma unroll
        for (int o = 4; o > 0; o >>= 1) wv += __shfl_xor_sync(0xff, wv, o);
        if (tid == 0) out[0] = (float)wv;
    }
}

// ---------------------------------------------------------------------------
extern "C" void kernel_launch(void* const* d_in, const int* in_sizes, int n_in,
                              void* d_out, int out_size) {
    const float* X = (const float*)d_in[0];
    const float* sp = (const float*)d_in[1];
    const float* trans = (const float*)d_in[2];
    const float* mu = (const float*)d_in[3];
    const float* log_var = (const float*)d_in[4];

    hmm_prep_kernel<<<8, 256>>>(sp, trans, mu, log_var);

    cudaLaunchAttribute at[1];
    at[0].id = cudaLaunchAttributeProgrammaticStreamSerialization;
    at[0].val.programmaticStreamSerializationAllowed = 1;

    cudaLaunchConfig_t cfg = {};
    cfg.attrs = at;
    cfg.numAttrs = 1;
    cfg.stream = 0;
    cfg.gridDim = dim3(GB);
    cfg.blockDim = dim3(256);
    float* outp = (float*)d_out;
    cudaLaunchKernelEx(&cfg, hmm_fused_kernel, X, outp);
}

// round 16
// speedup vs baseline: 1.1000x; 1.0553x over previous
#include <cuda_runtime.h>
#include <cuda_bf16.h>
#include <math.h>
#include <stdint.h>

#define BB 64
#define TT 4096
#define DD 90
#define KK 32
#define CC 128           // chunks per batch (R12-validated)
#define CHUNK 32         // TT / CC
#define WARM 8           // burn-in steps
#define NSTEP (WARM + CHUNK)     // 40
#define PADF 8           // MUST == WARM
#define PADB 8
#define ERows (PADF + TT + PADB) // 4112 rows per batch
#define NEB (BB * TT / 128)      // 2048 emission blocks
#define LOG2PI_F 1.8378770664093453f
#define FULLMASK 0xffffffffu

// ---- scratch (__device__ globals; no allocations allowed) ----
__device__ __align__(16) __nv_bfloat16 g_ee16[BB * ERows * KK];
__device__ __align__(16) uint2 g_Wb[12 * 4 * 32];
__device__ __align__(16) float g_bias[KK];
__device__ float g_pi[KK];
__device__ float g_expA[KK * KK];
__device__ __align__(16) float g_partial2[BB * CC];
__device__ __align__(16) float g_emaxpart[NEB];

__device__ __forceinline__ float warpMax(float v) {
#pragma unroll
    for (int o = 16; o > 0; o >>= 1) v = fmaxf(v, __shfl_xor_sync(FULLMASK, v, o));
    return v;
}
__device__ __forceinline__ float warpSum(float v) {
#pragma unroll
    for (int o = 16; o > 0; o >>= 1) v += __shfl_xor_sync(FULLMASK, v, o);
    return v;
}
__device__ __forceinline__ uint32_t packbf2(float lo, float hi) {
    __nv_bfloat162 h = __floats2bfloat162_rn(lo, hi);
    return *reinterpret_cast<uint32_t*>(&h);
}
__device__ __forceinline__ __nv_bfloat162 bfu(uint32_t v) {
    return *reinterpret_cast<__nv_bfloat162*>(&v);
}
__device__ __forceinline__ uint32_t ubf(__nv_bfloat162 h) {
    return *reinterpret_cast<uint32_t*>(&h);
}
__device__ __forceinline__ uint32_t sqbf2(uint32_t v) {
    float2 f = __bfloat1622float2(bfu(v));
    return packbf2(f.x * f.x, f.y * f.y);
}
__device__ __forceinline__ void mma_bf16(float& d0, float& d1, float& d2, float& d3,
                                         uint32_t a0, uint32_t a1, uint32_t a2, uint32_t a3,
                                         uint32_t b0, uint32_t b1) {
    asm volatile("mma.sync.aligned.m16n8k16.row.col.f32.bf16.bf16.f32 "
                 "{%0,%1,%2,%3},{%4,%5,%6,%7},{%8,%9},{%0,%1,%2,%3};"
                 : "+f"(d0), "+f"(d1), "+f"(d2), "+f"(d3)
                 : "r"(a0), "r"(a1), "r"(a2), "r"(a3), "r"(b0), "r"(b1));
}
__device__ __forceinline__ void mma_bf16_z(float* d,
                                           uint32_t a0, uint32_t a1, uint32_t a2, uint32_t a3,
                                           uint32_t b0, uint32_t b1) {
    asm volatile("mma.sync.aligned.m16n8k16.row.col.f32.bf16.bf16.f32 "
                 "{%0,%1,%2,%3},{%4,%5,%6,%7},{%8,%9},{%10,%10,%10,%10};"
                 : "=f"(d[0]), "=f"(d[1]), "=f"(d[2]), "=f"(d[3])
                 : "r"(a0), "r"(a1), "r"(a2), "r"(a3), "r"(b0), "r"(b1), "f"(0.0f));
}

// ---------------------------------------------------------------------------
// Kernel 1: prep — grid 8 x 256 (unchanged from R12).
// ---------------------------------------------------------------------------
__global__ void __launch_bounds__(256) hmm_prep_kernel(
        const float* __restrict__ sp, const float* __restrict__ trans,
        const float* __restrict__ mu, const float* __restrict__ log_var) {
    cudaTriggerProgrammaticLaunchCompletion();
    int tid = threadIdx.x, wid = tid >> 5, lane = tid & 31;
    int gw = blockIdx.x * 8 + wid;

    if (gw < 32) {
        float v = trans[gw * KK + lane];
        float m = warpMax(v);
        float e = expf(v - m);
        float s = warpSum(e);
        g_expA[gw * KK + lane] = e / s;
        if (gw == 0) {
            float pv = sp[lane];
            float pm = warpMax(pv);
            float pe = expf(pv - pm);
            float ps = warpSum(pe);
            g_pi[lane] = pe / ps;
        }
    } else {
        int k = gw - 32;
        float acc = 0.0f;
        for (int d = lane; d < DD; d += 32) {
            float lv = log_var[k * DD + d];
            float iv = expf(-lv);
            float m = mu[k * DD + d];
            acc = fmaf(m * m, iv, acc + lv);
        }
        acc = warpSum(acc);
        if (lane == 0) g_bias[k] = -0.5f * (acc + (float)DD * LOG2PI_F);
    }

    int p = blockIdx.x * 256 + tid;
    if (p < 12 * 4 * 32) {
        int s = p >> 7;
        int rem = p & 127;
        int ln = rem & 31;
        int gid = ln >> 2, tig = ln & 3;
        int n = (rem >> 5) * 8 + gid;
        float w[4];
#pragma unroll
        for (int h = 0; h < 4; ++h) {
            int row = s * 16 + tig * 2 + (h >> 1) * 8 + (h & 1);
            float v = 0.f;
            if (row < 96) {
                int d = row;
                if (d < DD) v = mu[n * DD + d] * expf(-log_var[n * DD + d]);
            } else {
                int d = row - 96;
                if (d < DD) v = -0.5f * expf(-log_var[n * DD + d]);
            }
            w[h] = v;
        }
        g_Wb[p] = make_uint2(packbf2(w[0], w[1]), packbf2(w[2], w[3]));
    }
}

// ---------------------------------------------------------------------------
// Kernel 2: emissions (bf16 MMA). Occupancy-boosted: only X is staged in smem
// (23 KB, bf16); B-fragments + bias read via __ldg (L1-hot 12 KB table);
// __launch_bounds__(256,4) caps regs at 64 -> >=4 CTAs/SM.
// ---------------------------------------------------------------------------
__global__ void __launch_bounds__(256, 4) hmm_emis_kernel(const float* __restrict__ X) {
    cudaTriggerProgrammaticLaunchCompletion();
    __shared__ __align__(16) uint32_t xsb[128 * 45];   // 23.04 KB
    __shared__ float mred[8];

    int tid = threadIdx.x;
    int wid = tid >> 5, lane = tid & 31;
    int gid = lane >> 2, tig = lane & 3;

    {   // stage X tile (f32 -> bf16x2 on the fly) — independent of prep
        const float4* X4 = (const float4*)(X + (long)blockIdx.x * 128 * DD);
        uint2* xs2 = (uint2*)xsb;
#pragma unroll
        for (int i = 0; i < 11; ++i) {
            float4 v = X4[tid + 256 * i];
            xs2[tid + 256 * i] = make_uint2(packbf2(v.x, v.y), packbf2(v.z, v.w));
        }
        if (tid < 2880 - 2816) {
            float4 v = X4[tid + 2816];
            xs2[tid + 2816] = make_uint2(packbf2(v.x, v.y), packbf2(v.z, v.w));
        }
    }
    cudaGridDependencySynchronize();     // wait for prep's g_Wb / g_bias
    __syncthreads();

    const uint32_t* xr0 = xsb + (wid * 16 + gid) * 45;
    const uint32_t* xr1 = xr0 + 8 * 45;

    float acc[4][4];
#pragma unroll
    for (int nt = 0; nt < 4; ++nt)
#pragma unroll
        for (int i = 0; i < 4; ++i) acc[nt][i] = 0.f;

#pragma unroll
    for (int s = 0; s < 6; ++s) {
        int w0 = s * 8 + tig;
        int w1 = w0 + 4;
        bool v1 = (s * 16 + tig * 2 + 8) < DD;
        uint32_t a0 = xr0[w0];
        uint32_t a1 = xr1[w0];
        uint32_t a2 = v1 ? xr0[w1] : 0u;
        uint32_t a3 = v1 ? xr1[w1] : 0u;
        uint32_t q0 = sqbf2(a0), q1 = sqbf2(a1), q2 = sqbf2(a2), q3 = sqbf2(a3);
#pragma unroll
        for (int nt = 0; nt < 4; ++nt) {
            uint2 bb = __ldg(&g_Wb[(s * 4 + nt) * 32 + lane]);
            mma_bf16(acc[nt][0], acc[nt][1], acc[nt][2], acc[nt][3],
                     a0, a1, a2, a3, bb.x, bb.y);
        }
#pragma unroll
        for (int nt = 0; nt < 4; ++nt) {
            uint2 bb = __ldg(&g_Wb[((s + 6) * 4 + nt) * 32 + lane]);
            mma_bf16(acc[nt][0], acc[nt][1], acc[nt][2], acc[nt][3],
                     q0, q1, q2, q3, bb.x, bb.y);
        }
    }

    const float2* gb2 = (const float2*)g_bias;
    float m0 = -1e30f, m1 = -1e30f;
#pragma unroll
    for (int nt = 0; nt < 4; ++nt) {
        float2 bv = __ldg(gb2 + nt * 4 + tig);
        acc[nt][0] += bv.x; acc[nt][1] += bv.y;
        acc[nt][2] += bv.x; acc[nt][3] += bv.y;
        m0 = fmaxf(m0, fmaxf(acc[nt][0], acc[nt][1]));
        m1 = fmaxf(m1, fmaxf(acc[nt][2], acc[nt][3]));
    }
#pragma unroll
    for (int o = 1; o <= 2; o <<= 1) {
        m0 = fmaxf(m0, __shfl_xor_sync(FULLMASK, m0, o));
        m1 = fmaxf(m1, __shfl_xor_sync(FULLMASK, m1, o));
    }
    long r0 = (long)(blockIdx.x >> 5) * ERows + PADF
            + (blockIdx.x & 31) * 128 + wid * 16 + gid;
    long r1 = r0 + 8;
    uint4 o0, o1;
    o0.x = packbf2(__expf(acc[0][0] - m0), __expf(acc[0][1] - m0));
    o0.y = packbf2(__expf(acc[1][0] - m0), __expf(acc[1][1] - m0));
    o0.z = packbf2(__expf(acc[2][0] - m0), __expf(acc[2][1] - m0));
    o0.w = packbf2(__expf(acc[3][0] - m0), __expf(acc[3][1] - m0));
    o1.x = packbf2(__expf(acc[0][2] - m1), __expf(acc[0][3] - m1));
    o1.y = packbf2(__expf(acc[1][2] - m1), __expf(acc[1][3] - m1));
    o1.z = packbf2(__expf(acc[2][2] - m1), __expf(acc[2][3] - m1));
    o1.w = packbf2(__expf(acc[3][2] - m1), __expf(acc[3][3] - m1));
    ((uint4*)(g_ee16 + r0 * KK))[tig] = o0;
    ((uint4*)(g_ee16 + r1 * KK))[tig] = o1;

    float msum = (tig == 0) ? (m0 + m1) : 0.f;
    msum = warpSum(msum);
    if (lane == 0) mred[wid] = msum;
    __syncthreads();
    if (tid == 0) {
        float s = 0.f;
#pragma unroll
        for (int i = 0; i < 8; ++i) s += mred[i];
        g_emaxpart[blockIdx.x] = s;
    }
}

// ---------------------------------------------------------------------------
// Kernel 3: tensor-core chunked scan, CC=128 (R12-validated, unchanged).
// ---------------------------------------------------------------------------
__global__ void __launch_bounds__(128) hmm_scan_kernel() {
    cudaTriggerProgrammaticLaunchCompletion();
    cudaGridDependencySynchronize();     // wait for emission (and transitively prep)
    int wid = threadIdx.x >> 5;
    int w = blockIdx.x * 4 + wid;        // 0..511
    int lane = threadIdx.x & 31;
    int gid = lane >> 2, tig = lane & 3;
    int b = w >> 3;                      // 8 warps per batch
    int g = w & 7;
    int c0 = g * 16 + gid;
    int c1 = c0 + 8;
    const __nv_bfloat16* eb = g_ee16 + (long)b * (ERows * KK);

    uint32_t Bf[8][2];
#pragma unroll
    for (int ks = 0; ks < 2; ++ks)
#pragma unroll
        for (int nt = 0; nt < 4; ++nt) {
            int n = nt * 8 + gid;
            int r = ks * 16 + 2 * tig;
            Bf[ks * 4 + nt][0] = packbf2(g_expA[r * KK + n], g_expA[(r + 1) * KK + n]);
            Bf[ks * 4 + nt][1] = packbf2(g_expA[(r + 8) * KK + n], g_expA[(r + 9) * KK + n]);
        }

    uint32_t pk[4][2];
    {
        uint4 ei = ((const uint4*)(eb + (long)PADF * KK))[tig];
        uint32_t ec[4] = {ei.x, ei.y, ei.z, ei.w};
#pragma unroll
        for (int nt = 0; nt < 4; ++nt) {
            float i00 = 1.f, i01 = 1.f;
            if (c0 == 0) {
                float2 ef = __bfloat1622float2(bfu(ec[nt]));
                i00 = g_pi[nt * 8 + 2 * tig] * ef.x;
                i01 = g_pi[nt * 8 + 2 * tig + 1] * ef.y;
            }
            pk[nt][0] = packbf2(i00, i01);
            pk[nt][1] = packbf2(1.f, 1.f);
        }
    }

    int ilo0 = (c0 == 0) ? WARM : 0;
    int ihi1 = (c1 == CC - 1) ? (NSTEP - 1) : NSTEP;

    const __nv_bfloat16* pe0 = eb + (long)(c0 * CHUNK + 1) * KK;
    const __nv_bfloat16* pe1 = eb + (long)(c1 * CHUNK + 1) * KK;

    uint4 ring0[4], ring1[4];
#pragma unroll
    for (int s = 0; s < 4; ++s) {
        ring0[s] = ((const uint4*)(pe0 + (long)s * KK))[tig];
        ring1[s] = ((const uint4*)(pe1 + (long)s * KK))[tig];
    }

    float logZ0 = 0.f, logZ1 = 0.f;
    for (int blk = 0; blk < NSTEP / 8; ++blk) {      // 5 blocks
        const __nv_bfloat16* q0 = pe0 + (long)(blk * 8 + 4) * KK;
        const __nv_bfloat16* q1 = pe1 + (long)(blk * 8 + 4) * KK;
        bool doLog = (blk >= WARM / 8);
#pragma unroll
        for (int ii = 0; ii < 8; ++ii) {
            int i = blk * 8 + ii;
            float dA[4][4], dB[4][4];
#pragma unroll
            for (int nt = 0; nt < 4; ++nt)
                mma_bf16_z(dA[nt], pk[0][0], pk[0][1], pk[1][0], pk[1][1],
                           Bf[nt][0], Bf[nt][1]);
#pragma unroll
            for (int nt = 0; nt < 4; ++nt)
                mma_bf16_z(dB[nt], pk[2][0], pk[2][1], pk[3][0], pk[3][1],
                           Bf[4 + nt][0], Bf[4 + nt][1]);

            const int slot = ii & 3;
            uint4 e0 = ring0[slot], e1 = ring1[slot];
            ring0[slot] = ((const uint4*)(q0 + (long)ii * KK))[tig];
            ring1[slot] = ((const uint4*)(q1 + (long)ii * KK))[tig];
            uint32_t ec0[4] = {e0.x, e0.y, e0.z, e0.w};
            uint32_t ec1[4] = {e1.x, e1.y, e1.z, e1.w};

            __nv_bfloat162 n0[4], n1[4];
#pragma unroll
            for (int nt = 0; nt < 4; ++nt) {
                __nv_bfloat162 d0 = __floats2bfloat162_rn(dA[nt][0] + dB[nt][0],
                                                          dA[nt][1] + dB[nt][1]);
                __nv_bfloat162 d1 = __floats2bfloat162_rn(dA[nt][2] + dB[nt][2],
                                                          dA[nt][3] + dB[nt][3]);
                n0[nt] = __hmul2(d0, bfu(ec0[nt]));
                n1[nt] = __hmul2(d1, bfu(ec1[nt]));
            }

            bool val0 = (i >= ilo0);
            bool val1 = (i < ihi1);
            if (ii == 7) {
                float S0 = 0.f, S1 = 0.f;
#pragma unroll
                for (int nt = 0; nt < 4; ++nt) {
                    float2 a = __bfloat1622float2(n0[nt]);
                    float2 c = __bfloat1622float2(n1[nt]);
                    S0 += a.x + a.y;
                    S1 += c.x + c.y;
                }
#pragma unroll
                for (int o = 1; o <= 2; o <<= 1) {
                    S0 += __shfl_xor_sync(FULLMASK, S0, o);
                    S1 += __shfl_xor_sync(FULLMASK, S1, o);
                }
                bool ren0 = val0 && (doLog || c0 != 0);
                bool ren1 = val1;
                float sc0 = ren0 ? __frcp_rn(S0) : 1.f;
                float sc1 = ren1 ? __frcp_rn(S1) : 1.f;
                if (doLog && val0) logZ0 += __logf(S0);
                if (doLog && val1) logZ1 += __logf(S1);
                __nv_bfloat162 sb0 = __float2bfloat162_rn(sc0);
                __nv_bfloat162 sb1 = __float2bfloat162_rn(sc1);
#pragma unroll
                for (int nt = 0; nt < 4; ++nt) {
                    n0[nt] = __hmul2(n0[nt], sb0);
                    n1[nt] = __hmul2(n1[nt], sb1);
                }
            }
#pragma unroll
            for (int nt = 0; nt < 4; ++nt) {
                pk[nt][0] = val0 ? ubf(n0[nt]) : pk[nt][0];
                pk[nt][1] = val1 ? ubf(n1[nt]) : pk[nt][1];
            }
        }
    }

    float S0 = 0.f, S1 = 0.f;
#pragma unroll
    for (int nt = 0; nt < 4; ++nt) {
        float2 a = __bfloat1622float2(bfu(pk[nt][0]));
        float2 c = __bfloat1622float2(bfu(pk[nt][1]));
        S0 += a.x + a.y;
        S1 += c.x + c.y;
    }
#pragma unroll
    for (int o = 1; o <= 2; o <<= 1) {
        S0 += __shfl_xor_sync(FULLMASK, S0, o);
        S1 += __shfl_xor_sync(FULLMASK, S1, o);
    }
    if (tig == 0) {
        g_partial2[b * CC + c0] = logZ0 + __logf(S0);
        g_partial2[b * CC + c1] = logZ1 + __logf(S1);
    }
}

// ---------------------------------------------------------------------------
// Kernel 4: final scalar (deterministic fixed-order double reduction)
// ---------------------------------------------------------------------------
__global__ void __launch_bounds__(256) hmm_final_kernel(float* __restrict__ out) {
    cudaGridDependencySynchronize();
    __shared__ double red[8];
    int tid = threadIdx.x;
    double v = 0.0;
    const float4* p2 = (const float4*)g_partial2;
    const float4* pe = (const float4*)g_emaxpart;
#pragma unroll
    for (int i = tid; i < BB * CC / 4; i += 256) {
        float4 a = p2[i];
        v += (double)a.x + (double)a.y + (double)a.z + (double)a.w;
    }
#pragma unroll
    for (int i = tid; i < NEB / 4; i += 256) {
        float4 a = pe[i];
        v += (double)a.x + (double)a.y + (double)a.z + (double)a.w;
    }
#pragma unroll
    for (int o = 16; o > 0; o >>= 1) v += __shfl_xor_sync(FULLMASK, v, o);
    if ((tid & 31) == 0) red[tid >> 5] = v;
    __syncthreads();
    if (tid < 8) {
        double wv = red[tid];
#pragma unroll
        for (int o = 4; o > 0; o >>= 1) wv += __shfl_xor_sync(0xff, wv, o);
        if (tid == 0) out[0] = (float)wv;
    }
}

// ---------------------------------------------------------------------------
extern "C" void kernel_launch(void* const* d_in, const int* in_sizes, int n_in,
                              void* d_out, int out_size) {
    const float* X = (const float*)d_in[0];
    const float* sp = (const float*)d_in[1];
    const float* trans = (const float*)d_in[2];
    const float* mu = (const float*)d_in[3];
    const float* log_var = (const float*)d_in[4];

    hmm_prep_kernel<<<8, 256>>>(sp, trans, mu, log_var);

    cudaLaunchAttribute at[1];
    at[0].id = cudaLaunchAttributeProgrammaticStreamSerialization;
    at[0].val.programmaticStreamSerializationAllowed = 1;

    cudaLaunchConfig_t cfg = {};
    cfg.attrs = at;
    cfg.numAttrs = 1;
    cfg.stream = 0;

    cfg.gridDim = dim3(NEB);
    cfg.blockDim = dim3(256);
    cudaLaunchKernelEx(&cfg, hmm_emis_kernel, X);

    cfg.gridDim = dim3(BB * CC / 64);   // 128 blocks x 4 warps
    cfg.blockDim = dim3(128);
    cudaLaunchKernelEx(&cfg, hmm_scan_kernel);

    cfg.gridDim = dim3(1);
    cfg.blockDim = dim3(256);
    float* outp = (float*)d_out;
    cudaLaunchKernelEx(&cfg, hmm_final_kernel, outp);
}